// round 3
// baseline (speedup 1.0000x reference)
#include <cuda_runtime.h>

#define NB    32
#define C_IN  64
#define HH    64
#define WWW   64
#define C_OUT 128
#define CONN  4

__global__ __launch_bounds__(256) void lp_conv_bt_kernel(
    const float* __restrict__ x,      // (32,64,64,64)
    const float* __restrict__ w,      // (128,4)
    const float* __restrict__ bias,   // (128)
    const int*   __restrict__ conn,   // (128,4)
    float*       __restrict__ out)    // (32,128,64,64)
{
    const int tx  = threadIdx.x;          // 0..3  -> 16-wide wo segment
    const int ho  = threadIdx.y;          // 0..63
    const int b   = blockIdx.x;
    const int co  = blockIdx.y;
    const int wo0 = tx * 16;

    float acc[16];
    #pragma unroll
    for (int i = 0; i < 16; ++i) acc[i] = 0.f;   // |.| >= 0: safe identity

    #pragma unroll
    for (int j = 0; j < CONN; ++j) {
        const int   idx = __ldg(&conn[co * CONN + j]);
        const float wj  = __ldg(&w[co * CONN + j]);

        // decode (c, di, dj) -- uniform across the block (co fixed)
        const int c   = idx / 9;
        const int rem = idx - c * 9;
        const int di  = rem / 3;
        const int dj  = rem - di * 3;

        // edge pad: pad_l = pad_r = 1 -> clamp source row into [0,63]
        const int sh = min(max(ho + di - 1, 0), HH - 1);
        const float* __restrict__ row = x + (((b * C_IN + c) * HH + sh) * WWW);

        // window registers: va[k] = row[wo0 + k - 1], k = 0..17 (clamped at edges)
        float va[18];
        {
            const float4 p0 = __ldg(reinterpret_cast<const float4*>(row + wo0));
            const float4 p1 = __ldg(reinterpret_cast<const float4*>(row + wo0 + 4));
            const float4 p2 = __ldg(reinterpret_cast<const float4*>(row + wo0 + 8));
            const float4 p3 = __ldg(reinterpret_cast<const float4*>(row + wo0 + 12));
            va[1]=p0.x;  va[2]=p0.y;  va[3]=p0.z;  va[4]=p0.w;
            va[5]=p1.x;  va[6]=p1.y;  va[7]=p1.z;  va[8]=p1.w;
            va[9]=p2.x;  va[10]=p2.y; va[11]=p2.z; va[12]=p2.w;
            va[13]=p3.x; va[14]=p3.y; va[15]=p3.z; va[16]=p3.w;
        }

        // output i needs row[wo0 + i + dj - 1] = va[i + dj]; dj is warp-uniform
        if (dj == 1) {
            #pragma unroll
            for (int i = 0; i < 16; ++i)
                acc[i] = fmaxf(acc[i], fabsf(wj - va[i + 1]));
        } else if (dj == 0) {
            va[0] = __ldg(&row[max(wo0 - 1, 0)]);      // clamp wo=-1 -> 0
            #pragma unroll
            for (int i = 0; i < 16; ++i)
                acc[i] = fmaxf(acc[i], fabsf(wj - va[i]));
        } else { // dj == 2
            va[17] = __ldg(&row[min(wo0 + 16, WWW - 1)]);  // clamp wo=64 -> 63
            #pragma unroll
            for (int i = 0; i < 16; ++i)
                acc[i] = fmaxf(acc[i], fabsf(wj - va[i + 2]));
        }
    }

    const float bs = __ldg(&bias[co]);
    float* __restrict__ op = out + (((long long)(b * C_OUT + co) * HH + ho) * WWW + wo0);
    #pragma unroll
    for (int q = 0; q < 4; ++q) {
        float4 r;
        r.x = acc[q*4+0] + bs;
        r.y = acc[q*4+1] + bs;
        r.z = acc[q*4+2] + bs;
        r.w = acc[q*4+3] + bs;
        reinterpret_cast<float4*>(op)[q] = r;
    }
}

extern "C" void kernel_launch(void* const* d_in, const int* in_sizes, int n_in,
                              void* d_out, int out_size)
{
    const float* x    = (const float*)d_in[0];
    const float* w    = (const float*)d_in[1];
    const float* bias = (const float*)d_in[2];
    const int*   conn = (const int*)  d_in[3];
    float*       out  = (float*)d_out;

    dim3 block(4, 64);            // 256 threads: 4 x 16-wide segments, 64 rows
    dim3 grid(NB, C_OUT);         // (32, 128): one block per (b, co) image
    lp_conv_bt_kernel<<<grid, block>>>(x, w, bias, conn, out);
}

// round 4
// speedup vs baseline: 2.4949x; 2.4949x over previous
#include <cuda_runtime.h>

#define NB    32
#define C_IN  64
#define HH    64
#define WWW   64
#define C_OUT 128
#define CONN  4

// Decoded connection descriptors: {c*HH*WWW, di-1, dj, w_bits}
__device__ int4 g_desc[C_OUT * CONN];

__global__ void prep_kernel(const float* __restrict__ w, const int* __restrict__ conn)
{
    const int t = threadIdx.x + blockIdx.x * blockDim.x;   // 0..511
    if (t >= C_OUT * CONN) return;
    const int idx = conn[t];
    const int c   = idx / 9;
    const int rem = idx - c * 9;
    const int di  = rem / 3;
    const int dj  = rem - di * 3;
    int4 d;
    d.x = c * HH * WWW;
    d.y = di - 1;
    d.z = dj;
    d.w = __float_as_int(w[t]);
    g_desc[t] = d;
}

__global__ __launch_bounds__(256) void lp_main(
    const float* __restrict__ x,      // (32,64,64,64)
    const float* __restrict__ bias,   // (128)
    float*       __restrict__ out)    // (32,128,64,64)
{
    const int qx  = threadIdx.x;                  // 0..15 -> wo quad
    const int ho  = blockIdx.x * 16 + threadIdx.y;
    const int b   = blockIdx.y;
    const int co  = blockIdx.z;
    const int wo0 = qx * 4;

    // 4 broadcast descriptor loads (uniform per block)
    const int4 d0 = g_desc[co * CONN + 0];
    const int4 d1 = g_desc[co * CONN + 1];
    const int4 d2 = g_desc[co * CONN + 2];
    const int4 d3 = g_desc[co * CONN + 3];
    const float bs = __ldg(&bias[co]);

    const float* __restrict__ xb = x + ((long long)b * (C_IN * HH * WWW)) + wo0;

    // batch all 4 gathers: compute addresses, issue loads (MLP=4)
    const int sh0 = min(max(ho + d0.y, 0), HH - 1);
    const int sh1 = min(max(ho + d1.y, 0), HH - 1);
    const int sh2 = min(max(ho + d2.y, 0), HH - 1);
    const int sh3 = min(max(ho + d3.y, 0), HH - 1);
    const float4 v0 = __ldg(reinterpret_cast<const float4*>(xb + d0.x + sh0 * WWW));
    const float4 v1 = __ldg(reinterpret_cast<const float4*>(xb + d1.x + sh1 * WWW));
    const float4 v2 = __ldg(reinterpret_cast<const float4*>(xb + d2.x + sh2 * WWW));
    const float4 v3 = __ldg(reinterpret_cast<const float4*>(xb + d3.x + sh3 * WWW));

    const bool pL = (qx == 0);
    const bool pR = (qx == 15);

    float a0 = 0.f, a1 = 0.f, a2 = 0.f, a3 = 0.f;   // |.| >= 0: safe identity

#define PROCESS(d, v)                                                          \
    {                                                                          \
        const float wj = __int_as_float(d.w);                                  \
        float e0, e1, e2, e3;                                                  \
        if (d.z == 1) {                                                        \
            e0 = v.x; e1 = v.y; e2 = v.z; e3 = v.w;                            \
        } else if (d.z == 0) {                                                 \
            float left = __shfl_up_sync(0xffffffffu, v.w, 1, 16);              \
            if (pL) left = v.x;     /* clamp wo=-1 -> wo=0 */                  \
            e0 = left; e1 = v.x; e2 = v.y; e3 = v.z;                           \
        } else {                                                               \
            float right = __shfl_down_sync(0xffffffffu, v.x, 1, 16);           \
            if (pR) right = v.w;    /* clamp wo=64 -> wo=63 */                 \
            e0 = v.y; e1 = v.z; e2 = v.w; e3 = right;                          \
        }                                                                      \
        a0 = fmaxf(a0, fabsf(wj - e0));                                        \
        a1 = fmaxf(a1, fabsf(wj - e1));                                        \
        a2 = fmaxf(a2, fabsf(wj - e2));                                        \
        a3 = fmaxf(a3, fabsf(wj - e3));                                        \
    }

    PROCESS(d0, v0)
    PROCESS(d1, v1)
    PROCESS(d2, v2)
    PROCESS(d3, v3)
#undef PROCESS

    float4 r;
    r.x = a0 + bs; r.y = a1 + bs; r.z = a2 + bs; r.w = a3 + bs;

    const long long obase = (((long long)(b * C_OUT + co) * HH + ho) * WWW + wo0);
    *reinterpret_cast<float4*>(out + obase) = r;
}

extern "C" void kernel_launch(void* const* d_in, const int* in_sizes, int n_in,
                              void* d_out, int out_size)
{
    const float* x    = (const float*)d_in[0];
    const float* w    = (const float*)d_in[1];
    const float* bias = (const float*)d_in[2];
    const int*   conn = (const int*)  d_in[3];
    float*       out  = (float*)d_out;

    prep_kernel<<<2, 256>>>(w, conn);

    dim3 block(16, 16);                  // warp = 2 rows x 64 wo (wavefront-optimal)
    dim3 grid(HH / 16, NB, C_OUT);       // (4, 32, 128)
    lp_main<<<grid, block>>>(x, bias, out);
}

// round 6
// speedup vs baseline: 2.6729x; 1.0714x over previous
#include <cuda_runtime.h>

#define NB    32
#define C_IN  64
#define HH    64
#define WWW   64
#define C_OUT 128
#define CONN  4

// Decoded connection descriptors: {c*HH*WWW, di-1, dj, w_bits}
__device__ int4 g_desc[C_OUT * CONN];

__global__ void prep_kernel(const float* __restrict__ w, const int* __restrict__ conn)
{
    const int t = threadIdx.x + blockIdx.x * blockDim.x;   // 0..511
    if (t >= C_OUT * CONN) return;
    const int idx = conn[t];
    const int c   = idx / 9;
    const int rem = idx - c * 9;
    const int di  = rem / 3;
    const int dj  = rem - di * 3;
    int4 d;
    d.x = c * HH * WWW;
    d.y = di - 1;
    d.z = dj;
    d.w = __float_as_int(w[t]);
    g_desc[t] = d;
}

__global__ __launch_bounds__(256) void lp_main(
    const float* __restrict__ x,      // (32,64,64,64)
    const float* __restrict__ bias,   // (128)
    float*       __restrict__ out)    // (32,128,64,64)
{
    const int qx   = threadIdx.x;                    // 0..15 -> wo quad
    const int hoA  = blockIdx.x * 32 + threadIdx.y;  // rows hoA and hoA+16
    const int hoB  = hoA + 16;
    const int b    = blockIdx.y;
    const int co   = blockIdx.z;
    const int wo0  = qx * 4;

    // 4 broadcast descriptor loads (uniform per block)
    const int4 d0 = g_desc[co * CONN + 0];
    const int4 d1 = g_desc[co * CONN + 1];
    const int4 d2 = g_desc[co * CONN + 2];
    const int4 d3 = g_desc[co * CONN + 3];
    const float bs = __ldg(&bias[co]);

    const float* __restrict__ xb = x + ((long long)b * (C_IN * HH * WWW)) + wo0;

    // batch all 8 gathers (MLP = 8)
    const int shA0 = min(max(hoA + d0.y, 0), HH - 1), shB0 = min(hoB + d0.y, HH - 1);
    const int shA1 = min(max(hoA + d1.y, 0), HH - 1), shB1 = min(hoB + d1.y, HH - 1);
    const int shA2 = min(max(hoA + d2.y, 0), HH - 1), shB2 = min(hoB + d2.y, HH - 1);
    const int shA3 = min(max(hoA + d3.y, 0), HH - 1), shB3 = min(hoB + d3.y, HH - 1);
    // (hoB >= 16, so hoB + d.y >= 15 -> no lower clamp needed on B rows)

    const float4 vA0 = __ldg(reinterpret_cast<const float4*>(xb + d0.x + shA0 * WWW));
    const float4 vB0 = __ldg(reinterpret_cast<const float4*>(xb + d0.x + shB0 * WWW));
    const float4 vA1 = __ldg(reinterpret_cast<const float4*>(xb + d1.x + shA1 * WWW));
    const float4 vB1 = __ldg(reinterpret_cast<const float4*>(xb + d1.x + shB1 * WWW));
    const float4 vA2 = __ldg(reinterpret_cast<const float4*>(xb + d2.x + shA2 * WWW));
    const float4 vB2 = __ldg(reinterpret_cast<const float4*>(xb + d2.x + shB2 * WWW));
    const float4 vA3 = __ldg(reinterpret_cast<const float4*>(xb + d3.x + shA3 * WWW));
    const float4 vB3 = __ldg(reinterpret_cast<const float4*>(xb + d3.x + shB3 * WWW));

    const bool pL = (qx == 0);
    const bool pR = (qx == 15);

    float aA0 = 0.f, aA1 = 0.f, aA2 = 0.f, aA3 = 0.f;  // |.| >= 0: safe identity
    float aB0 = 0.f, aB1 = 0.f, aB2 = 0.f, aB3 = 0.f;

#define PROCESS(d, va, vb)                                                     \
    {                                                                          \
        const float wj = __int_as_float(d.w);                                  \
        float eA0, eA1, eA2, eA3, eB0, eB1, eB2, eB3;                          \
        if (d.z == 1) {                                                        \
            eA0 = va.x; eA1 = va.y; eA2 = va.z; eA3 = va.w;                    \
            eB0 = vb.x; eB1 = vb.y; eB2 = vb.z; eB3 = vb.w;                    \
        } else if (d.z == 0) {                                                 \
            float lA = __shfl_up_sync(0xffffffffu, va.w, 1, 16);               \
            float lB = __shfl_up_sync(0xffffffffu, vb.w, 1, 16);               \
            if (pL) { lA = va.x; lB = vb.x; }  /* clamp wo=-1 -> wo=0 */       \
            eA0 = lA;  eA1 = va.x; eA2 = va.y; eA3 = va.z;                     \
            eB0 = lB;  eB1 = vb.x; eB2 = vb.y; eB3 = vb.z;                     \
        } else {                                                               \
            float rA = __shfl_down_sync(0xffffffffu, va.x, 1, 16);             \
            float rB = __shfl_down_sync(0xffffffffu, vb.x, 1, 16);             \
            if (pR) { rA = va.w; rB = vb.w; }  /* clamp wo=64 -> wo=63 */      \
            eA0 = va.y; eA1 = va.z; eA2 = va.w; eA3 = rA;                      \
            eB0 = vb.y; eB1 = vb.z; eB2 = vb.w; eB3 = rB;                      \
        }                                                                      \
        aA0 = fmaxf(aA0, fabsf(wj - eA0));                                     \
        aA1 = fmaxf(aA1, fabsf(wj - eA1));                                     \
        aA2 = fmaxf(aA2, fabsf(wj - eA2));                                     \
        aA3 = fmaxf(aA3, fabsf(wj - eA3));                                     \
        aB0 = fmaxf(aB0, fabsf(wj - eB0));                                     \
        aB1 = fmaxf(aB1, fabsf(wj - eB1));                                     \
        aB2 = fmaxf(aB2, fabsf(wj - eB2));                                     \
        aB3 = fmaxf(aB3, fabsf(wj - eB3));                                     \
    }

    PROCESS(d0, vA0, vB0)
    PROCESS(d1, vA1, vB1)
    PROCESS(d2, vA2, vB2)
    PROCESS(d3, vA3, vB3)
#undef PROCESS

    const long long ob = (((long long)(b * C_OUT + co) * HH + hoA) * WWW + wo0);
    float4 rA, rB;
    rA.x = aA0 + bs; rA.y = aA1 + bs; rA.z = aA2 + bs; rA.w = aA3 + bs;
    rB.x = aB0 + bs; rB.y = aB1 + bs; rB.z = aB2 + bs; rB.w = aB3 + bs;
    *reinterpret_cast<float4*>(out + ob)              = rA;
    *reinterpret_cast<float4*>(out + ob + 16 * WWW)   = rB;
}

extern "C" void kernel_launch(void* const* d_in, const int* in_sizes, int n_in,
                              void* d_out, int out_size)
{
    const float* x    = (const float*)d_in[0];
    const float* w    = (const float*)d_in[1];
    const float* bias = (const float*)d_in[2];
    const int*   conn = (const int*)  d_in[3];
    float*       out  = (float*)d_out;

    prep_kernel<<<2, 256>>>(w, conn);

    dim3 block(16, 16);                  // half-warp = contiguous 64-wo row
    dim3 grid(HH / 32, NB, C_OUT);       // (2, 32, 128); each thread: 2 rows
    lp_main<<<grid, block>>>(x, bias, out);
}